// round 17
// baseline (speedup 1.0000x reference)
#include <cuda_runtime.h>
#include <cuda_bf16.h>
#include <cstdint>
#include <cstddef>

// ---------------- problem constants ----------------
#define Nn    32768
#define Dd    512
#define D2    1024
#define FIN   64
#define DOUT  128
#define EPS_MSG 1e-7f
#define EPS_LN  1e-5f

#define CHUNK_ROWS 512
#define NCHUNK (Nn / CHUNK_ROWS)   // 64

// ---------------- scratch (device globals; no allocation allowed) ----------------
__device__ float g_x[(size_t)Nn * Dd];
__device__ float g_z[(size_t)Nn * D2];
__device__ float g_a[(size_t)Nn * D2];     // tf32-rounded fp32 A-operand buffer
#define OFF_ENC   0
#define OFF_W1_0  32768
#define OFF_W2_0  557056
#define OFF_W1_1  1081344
#define OFF_W2_1  1605632
#define OFF_WF    2129920
#define WTOT      2195456
__device__ float g_wt[WTOT];
__device__ float g_pm [NCHUNK * Dd];
__device__ float g_pse[NCHUNK * Dd];
__device__ float g_psm[NCHUNK * Dd];
__device__ float g_agg [Dd];
__device__ float g_bias1[D2];

// ---------------- PTX helpers ----------------
__device__ __forceinline__ uint32_t smem_u32(const void* p) {
    uint32_t a;
    asm("{ .reg .u64 t; cvta.to.shared.u64 t, %1; cvt.u32.u64 %0, t; }" : "=r"(a) : "l"(p));
    return a;
}

__device__ __forceinline__ float tf32r(float x) {
    uint32_t u;
    asm("cvt.rna.tf32.f32 %0, %1;" : "=r"(u) : "f"(x));
    return __uint_as_float(u);
}

__device__ __forceinline__ void cpa16(uint32_t saddr, const void* gaddr) {
    asm volatile("cp.async.cg.shared.global [%0], [%1], 16;"
                 :: "r"(saddr), "l"(__cvta_generic_to_global(gaddr)));
}
#define CP_COMMIT() asm volatile("cp.async.commit_group;" ::: "memory")
#define CP_WAIT1()  asm volatile("cp.async.wait_group 1;" ::: "memory")
#define CP_WAIT0()  asm volatile("cp.async.wait_group 0;" ::: "memory")

__device__ __forceinline__ void ldsm4(uint32_t& r0, uint32_t& r1, uint32_t& r2, uint32_t& r3,
                                      uint32_t addr) {
    asm volatile("ldmatrix.sync.aligned.m8n8.x4.shared.b16 {%0,%1,%2,%3}, [%4];"
                 : "=r"(r0), "=r"(r1), "=r"(r2), "=r"(r3) : "r"(addr));
}

__device__ __forceinline__ void mma_tf32(float* d, const uint32_t* a, const uint32_t* b) {
    asm volatile("mma.sync.aligned.m16n8k8.row.col.f32.tf32.tf32.f32 "
                 "{%0,%1,%2,%3}, {%4,%5,%6,%7}, {%8,%9}, {%0,%1,%2,%3};"
                 : "+f"(d[0]), "+f"(d[1]), "+f"(d[2]), "+f"(d[3])
                 : "r"(a[0]), "r"(a[1]), "r"(a[2]), "r"(a[3]), "r"(b[0]), "r"(b[1]));
}

// ---------------- tf32 tensor-core GEMM via mma.sync ----------------
// C[M,N] = A[M,K] @ B^T, B stored [N,K] K-major, operands tf32-rounded fp32.
// CTA 128m x 64n, 256 thr, 8 warps (4m x 2n), warp tile 32x32. K-chunk 32.
// 3-stage cp.async pipeline, prefetch distance 2 (wait_group 1 at chunk top),
// one __syncthreads per chunk. stage = A 16KB + B 8KB = 24KB; 3 stages = 72KB -> 2 CTAs/SM.
#define STG32 24576u
template<int EPI>
__global__ void __launch_bounds__(256, 2)
tgemm_k(const float* __restrict__ A, const float* __restrict__ B,
        const float* __restrict__ bias, const float* __restrict__ Cin,
        float* __restrict__ C, int K, int N)
{
    extern __shared__ char sm[];
    const uint32_t sb = smem_u32(sm);
    const int tid = threadIdx.x;
    const int lane = tid & 31;
    const int wid = tid >> 5;
    const int wm = (wid >> 1) * 32;
    const int wn = (wid & 1) * 32;
    const size_t rowBase = (size_t)blockIdx.y * 128;
    const int    colBase = blockIdx.x * 64;
    const int KC = K >> 5;

    const float* gA = A + rowBase * (size_t)K;
    const float* gB = B + (size_t)colBase * K;

    float acc[2][4][4];
    #pragma unroll
    for (int i = 0; i < 2; ++i)
        #pragma unroll
        for (int j = 0; j < 4; ++j)
            #pragma unroll
            for (int q = 0; q < 4; ++q) acc[i][j][q] = 0.f;

    auto load_stage = [&](uint32_t base, int k0) {
        #pragma unroll
        for (int i = 0; i < 4; ++i) {               // A: 128 rows x 8 segs
            int seg = tid + i * 256;
            int r = seg >> 3, s = seg & 7;
            uint32_t phys = (uint32_t)r * 128u + (((uint32_t)s * 16u) ^ (((uint32_t)(r & 7)) << 4));
            cpa16(base + phys, gA + (size_t)r * K + k0 + s * 4);
        }
        #pragma unroll
        for (int i = 0; i < 2; ++i) {               // B: 64 rows x 8 segs
            int seg = tid + i * 256;
            int r = seg >> 3, s = seg & 7;
            uint32_t phys = (uint32_t)r * 128u + (((uint32_t)s * 16u) ^ (((uint32_t)(r & 7)) << 4));
            cpa16(base + 16384u + phys, gB + (size_t)r * K + k0 + s * 4);
        }
    };

    load_stage(sb, 0);
    CP_COMMIT();
    if (KC > 1) { load_stage(sb + STG32, 32); CP_COMMIT(); }

    const int lrA = lane & 15;
    const int lcA = lane >> 4;
    const int nrOff = ((lane >> 4) & 1) * 8 + (lane & 7);
    const int kbOff = ((lane >> 3) & 1) * 16;

    for (int c = 0; c < KC; ++c) {
        if (c + 1 < KC) { CP_WAIT1(); } else { CP_WAIT0(); }
        __syncthreads();

        int sidx = c % 3;
        const uint32_t aA = sb + (uint32_t)sidx * STG32;
        const uint32_t aB = aA + 16384u;

        #pragma unroll
        for (int kk = 0; kk < 4; ++kk) {
            uint32_t af[2][4], bf[4][2];
            #pragma unroll
            for (int mt = 0; mt < 2; ++mt) {
                int row = wm + mt * 16 + lrA;
                uint32_t cb = (uint32_t)(kk * 32 + lcA * 16);
                uint32_t addr = aA + (uint32_t)row * 128u + (cb ^ (((uint32_t)(row & 7)) << 4));
                ldsm4(af[mt][0], af[mt][1], af[mt][2], af[mt][3], addr);
            }
            #pragma unroll
            for (int np = 0; np < 2; ++np) {
                int nrow = wn + np * 16 + nrOff;
                uint32_t kb = (uint32_t)(kk * 32 + kbOff);
                uint32_t addr = aB + (uint32_t)nrow * 128u + (kb ^ (((uint32_t)(nrow & 7)) << 4));
                uint32_t r0, r1, r2, r3;
                ldsm4(r0, r1, r2, r3, addr);
                bf[np * 2][0] = r0;     bf[np * 2][1] = r1;
                bf[np * 2 + 1][0] = r2; bf[np * 2 + 1][1] = r3;
            }
            #pragma unroll
            for (int mt = 0; mt < 2; ++mt)
                #pragma unroll
                for (int nt = 0; nt < 4; ++nt)
                    mma_tf32(acc[mt][nt], af[mt], bf[nt]);
            if (kk == 0 && c + 2 < KC) {
                load_stage(sb + (uint32_t)((c + 2) % 3) * STG32, (c + 2) * 32);
                CP_COMMIT();
            }
        }
    }

    // ---------------- epilogue ----------------
    __syncthreads();
    const int l4 = lane >> 2;
    const int l2 = (lane & 3) * 2;
    float2 bv[4];
    #pragma unroll
    for (int nt = 0; nt < 4; ++nt)
        bv[nt] = *(const float2*)(bias + colBase + wn + nt * 8 + l2);

    #pragma unroll
    for (int mt = 0; mt < 2; ++mt) {
        const size_t m0 = rowBase + wm + mt * 16 + l4;
        #pragma unroll
        for (int nt = 0; nt < 4; ++nt) {
            const int n = colBase + wn + nt * 8 + l2;
            float2 o0, o1;
            o0.x = acc[mt][nt][0] + bv[nt].x; o0.y = acc[mt][nt][1] + bv[nt].y;
            o1.x = acc[mt][nt][2] + bv[nt].x; o1.y = acc[mt][nt][3] + bv[nt].y;
            if (EPI == 1) {
                float2 c0 = *(const float2*)(Cin + m0 * (size_t)N + n);
                float2 c1 = *(const float2*)(Cin + (m0 + 8) * (size_t)N + n);
                o0.x += c0.x; o0.y += c0.y;
                o1.x += c1.x; o1.y += c1.y;
            }
            *(float2*)(C + m0 * (size_t)N + n)       = o0;
            *(float2*)(C + (m0 + 8) * (size_t)N + n) = o1;
        }
    }
}

// ---------------- fp32 -> tf32-rounded fp32 (optional relu) ----------------
template<int RELU>
__global__ void conv_k(const float* __restrict__ src, float* __restrict__ dst, int total4)
{
    int i = blockIdx.x * blockDim.x + threadIdx.x;
    if (i >= total4) return;
    float4 v = ((const float4*)src)[i];
    if (RELU) {
        v.x = fmaxf(v.x, 0.f); v.y = fmaxf(v.y, 0.f);
        v.z = fmaxf(v.z, 0.f); v.w = fmaxf(v.w, 0.f);
    }
    v.x = tf32r(v.x); v.y = tf32r(v.y); v.z = tf32r(v.z); v.w = tf32r(v.w);
    ((float4*)dst)[i] = v;
}

// ---------------- batched weight transpose + tf32 round: 3 matrices per launch ----------------
// W[K,N] -> T[N,K], 32x32 tiles, block ranges [0,n0), [n0,n0+n1), rest.
__global__ void wtrans3_k(const float* __restrict__ W0, float* __restrict__ T0, int K0, int N0, int n0,
                          const float* __restrict__ W1, float* __restrict__ T1, int K1, int N1, int n1,
                          const float* __restrict__ W2, float* __restrict__ T2, int K2, int N2)
{
    __shared__ float tile[32][33];
    int b = blockIdx.x;
    const float* W; float* T; int K, N;
    if (b < n0)            { W = W0; T = T0; K = K0; N = N0; }
    else if (b < n0 + n1)  { b -= n0;      W = W1; T = T1; K = K1; N = N1; }
    else                   { b -= n0 + n1; W = W2; T = T2; K = K2; N = N2; }
    int tilesX = N >> 5;
    int k0 = (b / tilesX) * 32, nn0 = (b % tilesX) * 32;
    int tx = threadIdx.x, ty = threadIdx.y;
    #pragma unroll
    for (int i = ty; i < 32; i += 8)
        tile[i][tx] = W[(size_t)(k0 + i) * N + nn0 + tx];
    __syncthreads();
    #pragma unroll
    for (int i = ty; i < 32; i += 8)
        T[(size_t)(nn0 + i) * K + k0 + tx] = tf32r(tile[tx][i]);
}

// ---------------- fused: online softmax-agg partials + tf32(relu(x)) emission ----------------
__global__ void colagg_part_k(const float* __restrict__ x,
                              const float* __restrict__ tptr,
                              float* __restrict__ pm, float* __restrict__ pse,
                              float* __restrict__ psm, float* __restrict__ aout)
{
    const float t = *tptr;
    const int cl = threadIdx.x & 63;
    const int lane = threadIdx.x >> 6;
    const int c = blockIdx.x * 64 + cl;
    const int r0 = blockIdx.y * CHUNK_ROWS;
    float m = -1e30f, se = 0.f, sm = 0.f;
    for (int r = r0 + lane; r < r0 + CHUNK_ROWS; r += 4) {
        const size_t idx = (size_t)r * Dd + c;
        float v = x[idx];
        float rl = fmaxf(v, 0.f);
        aout[idx] = tf32r(rl);
        float val = rl + EPS_MSG;
        float a = t * val;
        if (a > m) {
            float sc = __expf(m - a);
            se *= sc; sm *= sc; m = a;
        }
        float e = __expf(a - m);
        se += e;
        sm = fmaf(e, val, sm);
    }
    __shared__ float s_m[256], s_se[256], s_sm[256];
    s_m[threadIdx.x] = m; s_se[threadIdx.x] = se; s_sm[threadIdx.x] = sm;
    __syncthreads();
    if (threadIdx.x < 64) {
        float M = s_m[cl];
        #pragma unroll
        for (int q = 1; q < 4; ++q) M = fmaxf(M, s_m[cl + q * 64]);
        float SE = 0.f, SM = 0.f;
        #pragma unroll
        for (int q = 0; q < 4; ++q) {
            float w = __expf(s_m[cl + q * 64] - M);
            SE = fmaf(s_se[cl + q * 64], w, SE);
            SM = fmaf(s_sm[cl + q * 64], w, SM);
        }
        pm [blockIdx.y * Dd + c] = M;
        pse[blockIdx.y * Dd + c] = SE;
        psm[blockIdx.y * Dd + c] = SM;
    }
}

__global__ void reduce_agg_k(const float* __restrict__ pm, const float* __restrict__ pse,
                             const float* __restrict__ psm, float* __restrict__ agg)
{
    int c = blockIdx.x * blockDim.x + threadIdx.x;
    if (c >= Dd) return;
    float M = -1e30f;
    #pragma unroll 4
    for (int ch = 0; ch < NCHUNK; ++ch) M = fmaxf(M, pm[ch * Dd + c]);
    float se = 0.f, sm = 0.f;
    #pragma unroll 4
    for (int ch = 0; ch < NCHUNK; ++ch) {
        float w = __expf(pm[ch * Dd + c] - M);
        se = fmaf(pse[ch * Dd + c], w, se);
        sm = fmaf(psm[ch * Dd + c], w, sm);
    }
    agg[c] = sm / se;
}

// ---------------- bias1c[n] = b1[n] + sum_k agg[k] * Wt[n,k] ----------------
__global__ void gemv_bias_k(const float* __restrict__ wt, const float* __restrict__ b1,
                            const float* __restrict__ agg, float* __restrict__ out, int K)
{
    const int n = blockIdx.x * 8 + (threadIdx.x >> 5);
    const int lane = threadIdx.x & 31;
    const float* p = wt + (size_t)n * K;
    float acc = 0.f;
    for (int k = lane; k < K; k += 32)
        acc = fmaf(agg[k], p[k], acc);
    #pragma unroll
    for (int o = 16; o; o >>= 1) acc += __shfl_xor_sync(0xffffffffu, acc, o);
    if (lane == 0) out[n] = b1[n] + acc;
}

// ---------------- fused LayerNorm + ReLU + tf32 round (row length 1024) ----------------
__global__ void ln_relu_k(const float* __restrict__ z,
                          const float* __restrict__ gam, const float* __restrict__ bet,
                          float* __restrict__ aout)
{
    __shared__ float2 sred[8];
    const size_t row = blockIdx.x;
    const float4* zr = (const float4*)(z + row * (size_t)D2);
    float4 v = zr[threadIdx.x];
    float s  = v.x + v.y + v.z + v.w;
    float ss = fmaf(v.x, v.x, fmaf(v.y, v.y, fmaf(v.z, v.z, v.w * v.w)));
    #pragma unroll
    for (int o = 16; o; o >>= 1) {
        s  += __shfl_xor_sync(0xffffffffu, s,  o);
        ss += __shfl_xor_sync(0xffffffffu, ss, o);
    }
    if ((threadIdx.x & 31) == 0) sred[threadIdx.x >> 5] = make_float2(s, ss);
    __syncthreads();
    float S = 0.f, SS = 0.f;
    #pragma unroll
    for (int i = 0; i < 8; ++i) { S += sred[i].x; SS += sred[i].y; }
    const float mu  = S * (1.f / 1024.f);
    const float var = SS * (1.f / 1024.f) - mu * mu;
    const float inv = rsqrtf(var + EPS_LN);
    const int c = threadIdx.x * 4;
    const float4 gg = *(const float4*)(gam + c);
    const float4 bb = *(const float4*)(bet + c);
    float4 o;
    o.x = tf32r(fmaxf(fmaf((v.x - mu) * inv, gg.x, bb.x), 0.f));
    o.y = tf32r(fmaxf(fmaf((v.y - mu) * inv, gg.y, bb.y), 0.f));
    o.z = tf32r(fmaxf(fmaf((v.z - mu) * inv, gg.z, bb.z), 0.f));
    o.w = tf32r(fmaxf(fmaf((v.w - mu) * inv, gg.w, bb.w), 0.f));
    *(float4*)(aout + row * (size_t)D2 + c) = o;
}

// ---------------- host launcher ----------------
extern "C" void kernel_launch(void* const* d_in, const int* in_sizes, int n_in,
                              void* d_out, int out_size)
{
    const float* batch = (const float*)d_in[0];
    const float* W_enc = (const float*)d_in[1];
    const float* b_enc = (const float*)d_in[2];
    const float* Wf    = (const float*)d_in[3];
    const float* bf    = (const float*)d_in[4];
    const float* t [2] = {(const float*)d_in[5],  (const float*)d_in[12]};
    const float* W1[2] = {(const float*)d_in[6],  (const float*)d_in[13]};
    const float* b1[2] = {(const float*)d_in[7],  (const float*)d_in[14]};
    const float* g [2] = {(const float*)d_in[8],  (const float*)d_in[15]};
    const float* be[2] = {(const float*)d_in[9],  (const float*)d_in[16]};
    const float* W2[2] = {(const float*)d_in[10], (const float*)d_in[17]};
    const float* b2[2] = {(const float*)d_in[11], (const float*)d_in[18]};

    float *x, *z, *a, *wt, *pm, *pse, *psm, *agg, *bias1;
    cudaGetSymbolAddress((void**)&x,     g_x);
    cudaGetSymbolAddress((void**)&z,     g_z);
    cudaGetSymbolAddress((void**)&a,     g_a);
    cudaGetSymbolAddress((void**)&wt,    g_wt);
    cudaGetSymbolAddress((void**)&pm,    g_pm);
    cudaGetSymbolAddress((void**)&pse,   g_pse);
    cudaGetSymbolAddress((void**)&psm,   g_psm);
    cudaGetSymbolAddress((void**)&agg,   g_agg);
    cudaGetSymbolAddress((void**)&bias1, g_bias1);

    const int SMEM = 3 * 24576;   // 73728 -> 2 CTAs/SM
    cudaFuncSetAttribute((const void*)tgemm_k<0>, cudaFuncAttributeMaxDynamicSharedMemorySize, SMEM);
    cudaFuncSetAttribute((const void*)tgemm_k<1>, cudaFuncAttributeMaxDynamicSharedMemorySize, SMEM);

    // [1] wtrans batch A (ENC 32 tiles + W1_0 512 + W2_0 512), [2] wtrans batch B,
    // [3] batch cvt, [4] encoder GEMM (profiled)
    wtrans3_k<<<1056, dim3(32,8)>>>(
        W_enc, wt + OFF_ENC,  FIN, Dd,  32,
        W1[0], wt + OFF_W1_0, Dd,  D2,  512,
        W2[0], wt + OFF_W2_0, D2,  Dd);
    wtrans3_k<<<1088, dim3(32,8)>>>(
        W1[1], wt + OFF_W1_1, Dd,  D2,  512,
        W2[1], wt + OFF_W2_1, D2,  Dd,  512,
        Wf,    wt + OFF_WF,   Dd,  DOUT);
    conv_k<0><<<(Nn * FIN / 4 + 255) / 256, 256>>>(batch, a, Nn * FIN / 4);
    tgemm_k<0><<<dim3(Dd/64, Nn/128), 256, SMEM>>>(a, wt + OFF_ENC, b_enc, nullptr, x, FIN, Dd);

    const size_t woff1[2] = {OFF_W1_0, OFF_W1_1};
    const size_t woff2[2] = {OFF_W2_0, OFF_W2_1};
    const dim3 gCol(Dd / 64, NCHUNK);

    for (int l = 0; l < 2; ++l) {
        // fused: softmax-agg partials + a = tf32(relu(x))
        colagg_part_k<<<gCol, 256>>>(x, t[l], pm, pse, psm, a);
        reduce_agg_k <<<2, 256>>>(pm, pse, psm, agg);
        gemv_bias_k<<<D2/8, 256>>>(wt + woff1[l], b1[l], agg, bias1, Dd);
        // z = a @ W1 + bias1c
        tgemm_k<0><<<dim3(D2/64, Nn/128), 256, SMEM>>>(a, wt + woff1[l], bias1, nullptr, z, Dd, D2);
        // a = tf32(relu(LN(z)))
        ln_relu_k<<<Nn, 256>>>(z, g[l], be[l], a);
        // x = x + a @ W2 + b2
        tgemm_k<1><<<dim3(Dd/64, Nn/128), 256, SMEM>>>(a, wt + woff2[l], b2[l], x, x, D2, Dd);
    }

    // ---- final: out = relu(x) @ Wf + bf ----
    conv_k<1><<<Nn * Dd / 4 / 256, 256>>>(x, a, Nn * Dd / 4);
    tgemm_k<0><<<dim3(DOUT/64, Nn/128), 256, SMEM>>>(a, wt + OFF_WF, bf, nullptr, (float*)d_out, Dd, DOUT);
}